// round 11
// baseline (speedup 1.0000x reference)
#include <cuda_runtime.h>
#include <cuda_bf16.h>
#include <cstdint>

// FlowNet correlation — R10: R9 banded parity-space Gram (mma.sync bf16 hi/lo)
// at 512 threads (4 warps/SMSP) via tile-split warps.
// out[b, dyi*21+dxi, h, w] = (1/256) * sum_c in1[b,c,h,w] * in2[b,c,h+dy,w+dx]
// Parity space: i = w>>1; band j - i = dxi-10 in [-10,10].
// Warp = (row-block rb, parity p, tile-half th): th=0 -> B tiles {0,1,2},
// th=1 -> {3,4}. No reduction needed (distinct output tiles).

#define CB   8
#define CC_  256
#define HH   96
#define WW   128
#define GG   21
#define DD   441
#define NTHR 512

#define QBLOB  131072L     // per (b,h):  [par][hl][kc][64 rows][128B]
#define KTILE  11264       // per (par,hl): 88 rows x 128B (halo rows zero)
#define KCHUNK 45056       // per kc: [par][hl] x KTILE
#define KBLOB  180224L     // per (b,r): 4 kc x KCHUNK

#define QOFF   0
#define KOFF   131072
#define SDOFF  221184                  // 21*128 f32 dump
#define SMEM_REQ 232064

__device__ __align__(128) char g1[(long)CB * HH * QBLOB];
__device__ __align__(128) char g2[(long)CB * HH * KBLOB];

// ---------------- helpers ----------------
__device__ __forceinline__ uint32_t smem_u32(const void* p) {
    uint32_t a;
    asm("{ .reg .u64 t; cvta.to.shared.u64 t, %1; cvt.u32.u64 %0, t; }"
        : "=r"(a) : "l"(p));
    return a;
}
__device__ __forceinline__ void cp16(uint32_t dst, const void* src) {
    asm volatile("cp.async.cg.shared.global [%0], [%1], 16;"
                 :: "r"(dst), "l"(src));
}
__device__ __forceinline__ void cp_commit() {
    asm volatile("cp.async.commit_group;" ::: "memory");
}
__device__ __forceinline__ void cp_wait1() {
    asm volatile("cp.async.wait_group 1;" ::: "memory");
}
__device__ __forceinline__ void cp_wait0() {
    asm volatile("cp.async.wait_group 0;" ::: "memory");
}
__device__ __forceinline__ void ldmA(uint32_t a[4], uint32_t addr) {
    asm volatile("ldmatrix.sync.aligned.m8n8.x4.shared.b16 {%0,%1,%2,%3}, [%4];"
        : "=r"(a[0]), "=r"(a[1]), "=r"(a[2]), "=r"(a[3]) : "r"(addr));
}
__device__ __forceinline__ void ldmB(uint32_t bq[2], uint32_t addr) {
    asm volatile("ldmatrix.sync.aligned.m8n8.x2.shared.b16 {%0,%1}, [%2];"
        : "=r"(bq[0]), "=r"(bq[1]) : "r"(addr));
}
__device__ __forceinline__ void mma16816(float c[4], const uint32_t a[4],
                                         const uint32_t bq[2]) {
    asm volatile("mma.sync.aligned.m16n8k16.row.col.f32.bf16.bf16.f32 "
        "{%0,%1,%2,%3}, {%4,%5,%6,%7}, {%8,%9}, {%0,%1,%2,%3};"
        : "+f"(c[0]), "+f"(c[1]), "+f"(c[2]), "+f"(c[3])
        : "r"(a[0]), "r"(a[1]), "r"(a[2]), "r"(a[3]), "r"(bq[0]), "r"(bq[1]));
}
__device__ __forceinline__ unsigned short cvt_hl(float v, int hl) {
    const __nv_bfloat16 h = __float2bfloat16(v);
    if (!hl) return __bfloat16_as_ushort(h);
    return __bfloat16_as_ushort(__float2bfloat16(v - __bfloat162float(h)));
}

// ---------------- prepass: fp32 -> swizzled bf16 hi/lo parity tiles ----------
__global__ __launch_bounds__(512)
void prep_kernel(const float* __restrict__ in1,
                 const float* __restrict__ in2)
{
    __shared__ float st[64][132];
    const int kc = blockIdx.x, hh = blockIdx.y;
    const int b = blockIdx.z >> 1, inp = blockIdx.z & 1;
    const float* src = inp ? in2 : in1;

    for (int i = threadIdx.x; i < 64 * 32; i += 512) {
        const int c = i >> 5, q = i & 31;
        const float4 v = *reinterpret_cast<const float4*>(
            src + (((long)(b * CC_ + kc * 64 + c)) * HH + hh) * WW + 4 * q);
        st[c][4*q+0] = v.x; st[c][4*q+1] = v.y;
        st[c][4*q+2] = v.z; st[c][4*q+3] = v.w;
    }
    __syncthreads();

    if (!inp) {
        char* base = g1 + (long)(b * HH + hh) * QBLOB;
        for (int e = threadIdx.x; e < 2048; e += 512) {
            const int c8 = e & 7, s = (e >> 3) & 63;
            const int hl = (e >> 9) & 1, par = (e >> 10) & 1;
            const int w = 2 * s + par;
            uint32_t pk[4];
#pragma unroll
            for (int k = 0; k < 4; ++k) {
                const unsigned short u0 = cvt_hl(st[c8*8 + 2*k][w], hl);
                const unsigned short u1 = cvt_hl(st[c8*8 + 2*k + 1][w], hl);
                pk[k] = (uint32_t)u0 | ((uint32_t)u1 << 16);
            }
            char* tile = base + (long)(((par*2 + hl)*4 + kc)) * 8192;
            *reinterpret_cast<uint4*>(tile + s*128 + ((c8 ^ (s & 7)) << 4)) =
                make_uint4(pk[0], pk[1], pk[2], pk[3]);
        }
    } else {
        char* base = g2 + (long)(b * HH + hh) * KBLOB;
        for (int e = threadIdx.x; e < 2816; e += 512) {
            const int c8 = e & 7;
            const int jp = (e >> 3) % 88;
            const int hlp = e / (8 * 88);
            const int hl = hlp & 1, par = hlp >> 1;
            uint4 val = make_uint4(0u, 0u, 0u, 0u);
            if (jp >= 10 && jp < 74) {
                const int w = 2 * (jp - 10) + par;
                uint32_t pk[4];
#pragma unroll
                for (int k = 0; k < 4; ++k) {
                    const unsigned short u0 = cvt_hl(st[c8*8 + 2*k][w], hl);
                    const unsigned short u1 = cvt_hl(st[c8*8 + 2*k + 1][w], hl);
                    pk[k] = (uint32_t)u0 | ((uint32_t)u1 << 16);
                }
                val = make_uint4(pk[0], pk[1], pk[2], pk[3]);
            }
            char* tile = base + (long)(kc*4 + par*2 + hl) * KTILE;
            *reinterpret_cast<uint4*>(tile + jp*128 + ((c8 ^ (jp & 7)) << 4)) = val;
        }
    }
}

// ---------------- main kernel ----------------
__global__ __launch_bounds__(NTHR, 1)
void corr_mma_kernel(float* __restrict__ out)
{
    extern __shared__ char smraw[];
    const uint32_t rawS = smem_u32(smraw);
    const uint32_t smb = (rawS + 127) & ~127u;
    char* smA = smraw + (smb - rawS);

    const int tid = threadIdx.x, lane = tid & 31, wid = tid >> 5;
    const int h = blockIdx.x, b = blockIdx.y;
    const int p  = wid & 1;
    const int rb = (wid >> 1) & 3;
    const int th = wid >> 3;                  // tile-half: 0 -> {0,1,2}, 1 -> {3,4}
    const int i0 = rb * 16;
    const int tb = th ? 3 : 0;
    const int nt = th ? 2 : 3;

    const int dyimin = (h >= 20) ? 0 : ((21 - h) >> 1);
    const int dyimax = min(20, (115 - h) >> 1);
    const int nv = dyimax - dyimin + 1;
    const int NC = 4 * nv;

    const long obase_bh = (long)b * DD * HH * WW + (long)h * WW;

    // zero planes for invalid dy
    for (int dyi = 0; dyi < GG; ++dyi) {
        if (dyi >= dyimin && dyi <= dyimax) continue;
        const long pb = obase_bh + (long)(dyi * GG) * (HH * WW);
        for (int e = tid; e < GG * WW; e += NTHR) {
            out[pb + (long)(e >> 7) * (HH * WW) + (e & 127)] = 0.0f;
        }
    }

    // K chunk issue (one commit group per chunk)
    auto issueK = [&](int c, int stage) {
        const int vidx = c >> 2, kc = c & 3;
        const int r = h + 2 * (dyimin + vidx) - 20;
        const char* src = g2 + (long)(b * HH + r) * KBLOB + (long)kc * KCHUNK;
        const uint32_t dst = smb + KOFF + (uint32_t)stage * KCHUNK;
#pragma unroll
        for (int o = 0; o < 6; ++o) {
            const int t = tid + NTHR * o;
            if (t < 2816) cp16(dst + (uint32_t)t * 16, src + (long)t * 16);
        }
        cp_commit();
    };

    // prologue: Q (+K0) as group 0, K1 as group 1
    {
        const char* qsrc = g1 + (long)(b * HH + h) * QBLOB;
#pragma unroll
        for (int o = 0; o < 16; ++o) {
            const int t = tid + NTHR * o;
            cp16(smb + QOFF + (uint32_t)t * 16, qsrc + (long)t * 16);
        }
        const int r0v = h + 2 * dyimin - 20;
        const char* ks = g2 + (long)(b * HH + r0v) * KBLOB;
        const uint32_t dst = smb + KOFF;
#pragma unroll
        for (int o = 0; o < 6; ++o) {
            const int t = tid + NTHR * o;
            if (t < 2816) cp16(dst + (uint32_t)t * 16, ks + (long)t * 16);
        }
        cp_commit();
        issueK(1, 1);
    }

    // per-lane ldmatrix address constants (identical math to R9)
    const int matA = lane >> 3;
    const int rA   = (lane & 7) + ((matA & 1) << 3);
    const int ckA  = matA >> 1;
    const uint32_t aRow = (uint32_t)(i0 + rA) * 128;
    const int swA = lane & 7;
    const int rB = lane & 7;
    const int matB = (lane >> 3) & 1;
    const uint32_t bRow = (uint32_t)(i0 + rB) * 128;

    float C[3][4];
#pragma unroll
    for (int u = 0; u < 3; ++u)
#pragma unroll
        for (int g = 0; g < 4; ++g) C[u][g] = 0.0f;

    const float scale = 1.0f / 256.0f;
    float* sd = reinterpret_cast<float*>(smA + SDOFF);
    const int r0l = lane >> 2, n0l = (lane & 3) * 2;

    for (int c = 0; c < NC; ++c) {
        if (c + 1 < NC) cp_wait1(); else cp_wait0();
        __syncthreads();                       // stage (c&1) visible CTA-wide

        // ---- compute chunk c (this warp: tiles tb..tb+nt-1) ----
        {
            const int kc = c & 3;
            const uint32_t qhi = smb + QOFF + (uint32_t)((p*2 + 0)*4 + kc) * 8192;
            const uint32_t qlo = smb + QOFF + (uint32_t)((p*2 + 1)*4 + kc) * 8192;
            const uint32_t khi = smb + KOFF + (uint32_t)(c & 1) * KCHUNK
                               + (uint32_t)(p * 2) * KTILE;
            const uint32_t klo = khi + KTILE;
#pragma unroll
            for (int k = 0; k < 4; ++k) {
                uint32_t aH[4], aL[4], bH[2], bL[2];
                const uint32_t ao = aRow + ((uint32_t)((2*k + ckA) ^ swA) << 4);
                ldmA(aH, qhi + ao);
                ldmA(aL, qlo + ao);
                const uint32_t bo = bRow + ((uint32_t)((2*k + matB) ^ rB) << 4);
#pragma unroll
                for (int u = 0; u < 3; ++u) {
                    if (u >= nt) break;
                    const uint32_t toff = (uint32_t)(tb + u) * 1024;
                    ldmB(bH, khi + bo + toff);
                    mma16816(C[u], aH, bH);
                    mma16816(C[u], aL, bH);
                    ldmB(bL, klo + bo + toff);
                    mma16816(C[u], aH, bL);
                }
            }
        }

        // ---- epilogue after last kc of a dy ----
        if ((c & 3) == 3) {
            const int dyi = dyimin + (c >> 2);
#pragma unroll
            for (int u = 0; u < 3; ++u) {
                if (u >= nt) break;
                const int t = tb + u;
#pragma unroll
                for (int g = 0; g < 4; ++g) {
                    const int row = r0l + ((g & 2) ? 8 : 0);
                    const int col = n0l + (g & 1);
                    const int dxi = 8 * t + col - row;
                    if (dxi >= 0 && dxi < GG)
                        sd[dxi * WW + 2 * (i0 + row) + p] = C[u][g] * scale;
                    C[u][g] = 0.0f;
                }
            }
            __syncthreads();                    // sd complete
            const long pb = obase_bh + (long)(dyi * GG) * (HH * WW);
            for (int e = tid; e < GG * WW; e += NTHR) {
                out[pb + (long)(e >> 7) * (HH * WW) + (e & 127)] = sd[e];
            }
        }

        __syncthreads();                        // stage (c&1) drained; sd read
        if (c + 2 < NC) issueK(c + 2, c & 1);
    }
}

extern "C" void kernel_launch(void* const* d_in, const int* in_sizes, int n_in,
                              void* d_out, int out_size)
{
    const float* in1 = (const float*)d_in[0];
    const float* in2 = (const float*)d_in[1];
    float* out = (float*)d_out;
    (void)in_sizes; (void)n_in; (void)out_size;

    cudaFuncSetAttribute(corr_mma_kernel,
                         cudaFuncAttributeMaxDynamicSharedMemorySize, SMEM_REQ);

    dim3 pgrid(4, HH, CB * 2);
    prep_kernel<<<pgrid, 512>>>(in1, in2);

    dim3 grid(HH, CB);
    corr_mma_kernel<<<grid, NTHR, SMEM_REQ>>>(out);
}

// round 12
// speedup vs baseline: 1.0872x; 1.0872x over previous
#include <cuda_runtime.h>
#include <cuda_bf16.h>
#include <cstdint>

// FlowNet correlation — R11: banded parity-space Gram via mma.sync (bf16 hi/lo),
// 512 threads with BALANCED k-split warps (R10's tile-split doubled A-LDSM and
// was imbalanced). Warp = (row-block rb, parity p, k-half kh): kh=0 -> k{0,1},
// kh=1 -> k{2,3}; halves summed in the per-dy epilogue through sd.
// Prepass: 133-float smem pad (8-way -> 2-way read conflicts).

#define CB   8
#define CC_  256
#define HH   96
#define WW   128
#define GG   21
#define DD   441
#define NTHR 512

#define QBLOB  131072L     // per (b,h):  [par][hl][kc][64 rows][128B]
#define KTILE  11264       // per (par,hl): 88 rows x 128B (halo rows zero)
#define KCHUNK 45056       // per kc: [par][hl] x KTILE
#define KBLOB  180224L     // per (b,r): 4 kc x KCHUNK

#define QOFF   0
#define KOFF   131072
#define SDOFF  221184                  // 21*128 f32 dump (unscaled sum)
#define SMEM_REQ 232064

__device__ __align__(128) char g1[(long)CB * HH * QBLOB];
__device__ __align__(128) char g2[(long)CB * HH * KBLOB];

// ---------------- helpers ----------------
__device__ __forceinline__ uint32_t smem_u32(const void* p) {
    uint32_t a;
    asm("{ .reg .u64 t; cvta.to.shared.u64 t, %1; cvt.u32.u64 %0, t; }"
        : "=r"(a) : "l"(p));
    return a;
}
__device__ __forceinline__ void cp16(uint32_t dst, const void* src) {
    asm volatile("cp.async.cg.shared.global [%0], [%1], 16;"
                 :: "r"(dst), "l"(src));
}
__device__ __forceinline__ void cp_commit() {
    asm volatile("cp.async.commit_group;" ::: "memory");
}
__device__ __forceinline__ void cp_wait1() {
    asm volatile("cp.async.wait_group 1;" ::: "memory");
}
__device__ __forceinline__ void cp_wait0() {
    asm volatile("cp.async.wait_group 0;" ::: "memory");
}
__device__ __forceinline__ void ldmA(uint32_t a[4], uint32_t addr) {
    asm volatile("ldmatrix.sync.aligned.m8n8.x4.shared.b16 {%0,%1,%2,%3}, [%4];"
        : "=r"(a[0]), "=r"(a[1]), "=r"(a[2]), "=r"(a[3]) : "r"(addr));
}
__device__ __forceinline__ void ldmB(uint32_t bq[2], uint32_t addr) {
    asm volatile("ldmatrix.sync.aligned.m8n8.x2.shared.b16 {%0,%1}, [%2];"
        : "=r"(bq[0]), "=r"(bq[1]) : "r"(addr));
}
__device__ __forceinline__ void mma16816(float c[4], const uint32_t a[4],
                                         const uint32_t bq[2]) {
    asm volatile("mma.sync.aligned.m16n8k16.row.col.f32.bf16.bf16.f32 "
        "{%0,%1,%2,%3}, {%4,%5,%6,%7}, {%8,%9}, {%0,%1,%2,%3};"
        : "+f"(c[0]), "+f"(c[1]), "+f"(c[2]), "+f"(c[3])
        : "r"(a[0]), "r"(a[1]), "r"(a[2]), "r"(a[3]), "r"(bq[0]), "r"(bq[1]));
}
__device__ __forceinline__ unsigned short cvt_hl(float v, int hl) {
    const __nv_bfloat16 h = __float2bfloat16(v);
    if (!hl) return __bfloat16_as_ushort(h);
    return __bfloat16_as_ushort(__float2bfloat16(v - __bfloat162float(h)));
}

// ---------------- prepass: fp32 -> swizzled bf16 hi/lo parity tiles ----------
__global__ __launch_bounds__(256)
void prep_kernel(const float* __restrict__ in1,
                 const float* __restrict__ in2)
{
    __shared__ float st[64][133];          // 133 pad: 2-way read conflicts
    const int kc = blockIdx.x, hh = blockIdx.y;
    const int b = blockIdx.z >> 1, inp = blockIdx.z & 1;
    const float* src = inp ? in2 : in1;

    for (int i = threadIdx.x; i < 64 * 32; i += 256) {
        const int c = i >> 5, q = i & 31;
        const float4 v = *reinterpret_cast<const float4*>(
            src + (((long)(b * CC_ + kc * 64 + c)) * HH + hh) * WW + 4 * q);
        st[c][4*q+0] = v.x; st[c][4*q+1] = v.y;
        st[c][4*q+2] = v.z; st[c][4*q+3] = v.w;
    }
    __syncthreads();

    if (!inp) {
        char* base = g1 + (long)(b * HH + hh) * QBLOB;
        for (int e = threadIdx.x; e < 2048; e += 256) {
            const int c8 = e & 7, s = (e >> 3) & 63;
            const int hl = (e >> 9) & 1, par = (e >> 10) & 1;
            const int w = 2 * s + par;
            uint32_t pk[4];
#pragma unroll
            for (int k = 0; k < 4; ++k) {
                const unsigned short u0 = cvt_hl(st[c8*8 + 2*k][w], hl);
                const unsigned short u1 = cvt_hl(st[c8*8 + 2*k + 1][w], hl);
                pk[k] = (uint32_t)u0 | ((uint32_t)u1 << 16);
            }
            char* tile = base + (long)(((par*2 + hl)*4 + kc)) * 8192;
            *reinterpret_cast<uint4*>(tile + s*128 + ((c8 ^ (s & 7)) << 4)) =
                make_uint4(pk[0], pk[1], pk[2], pk[3]);
        }
    } else {
        char* base = g2 + (long)(b * HH + hh) * KBLOB;
        for (int e = threadIdx.x; e < 2816; e += 256) {
            const int c8 = e & 7;
            const int jp = (e >> 3) % 88;
            const int hlp = e / (8 * 88);
            const int hl = hlp & 1, par = hlp >> 1;
            uint4 val = make_uint4(0u, 0u, 0u, 0u);
            if (jp >= 10 && jp < 74) {
                const int w = 2 * (jp - 10) + par;
                uint32_t pk[4];
#pragma unroll
                for (int k = 0; k < 4; ++k) {
                    const unsigned short u0 = cvt_hl(st[c8*8 + 2*k][w], hl);
                    const unsigned short u1 = cvt_hl(st[c8*8 + 2*k + 1][w], hl);
                    pk[k] = (uint32_t)u0 | ((uint32_t)u1 << 16);
                }
                val = make_uint4(pk[0], pk[1], pk[2], pk[3]);
            }
            char* tile = base + (long)(kc*4 + par*2 + hl) * KTILE;
            *reinterpret_cast<uint4*>(tile + jp*128 + ((c8 ^ (jp & 7)) << 4)) = val;
        }
    }
}

// ---------------- main kernel ----------------
__global__ __launch_bounds__(NTHR, 1)
void corr_mma_kernel(float* __restrict__ out)
{
    extern __shared__ char smraw[];
    const uint32_t rawS = smem_u32(smraw);
    const uint32_t smb = (rawS + 127) & ~127u;
    char* smA = smraw + (smb - rawS);

    const int tid = threadIdx.x, lane = tid & 31, wid = tid >> 5;
    const int h = blockIdx.x, b = blockIdx.y;
    const int p  = wid & 1;
    const int rb = (wid >> 1) & 3;
    const int kh = wid >> 3;                  // k-half: 0 -> k{0,1}, 1 -> k{2,3}
    const int i0 = rb * 16;

    const int dyimin = (h >= 20) ? 0 : ((21 - h) >> 1);
    const int dyimax = min(20, (115 - h) >> 1);
    const int nv = dyimax - dyimin + 1;
    const int NC = 4 * nv;

    const long obase_bh = (long)b * DD * HH * WW + (long)h * WW;

    // zero planes for invalid dy
    for (int dyi = 0; dyi < GG; ++dyi) {
        if (dyi >= dyimin && dyi <= dyimax) continue;
        const long pb = obase_bh + (long)(dyi * GG) * (HH * WW);
        for (int e = tid; e < GG * WW; e += NTHR) {
            out[pb + (long)(e >> 7) * (HH * WW) + (e & 127)] = 0.0f;
        }
    }

    // K chunk issue (one commit group per chunk)
    auto issueK = [&](int c, int stage) {
        const int vidx = c >> 2, kc = c & 3;
        const int r = h + 2 * (dyimin + vidx) - 20;
        const char* src = g2 + (long)(b * HH + r) * KBLOB + (long)kc * KCHUNK;
        const uint32_t dst = smb + KOFF + (uint32_t)stage * KCHUNK;
#pragma unroll
        for (int o = 0; o < 6; ++o) {
            const int t = tid + NTHR * o;
            if (t < 2816) cp16(dst + (uint32_t)t * 16, src + (long)t * 16);
        }
        cp_commit();
    };

    // prologue: Q (+K0) as group 0, K1 as group 1
    {
        const char* qsrc = g1 + (long)(b * HH + h) * QBLOB;
#pragma unroll
        for (int o = 0; o < 16; ++o) {
            const int t = tid + NTHR * o;
            cp16(smb + QOFF + (uint32_t)t * 16, qsrc + (long)t * 16);
        }
        const int r0v = h + 2 * dyimin - 20;
        const char* ks = g2 + (long)(b * HH + r0v) * KBLOB;
        const uint32_t dst = smb + KOFF;
#pragma unroll
        for (int o = 0; o < 6; ++o) {
            const int t = tid + NTHR * o;
            if (t < 2816) cp16(dst + (uint32_t)t * 16, ks + (long)t * 16);
        }
        cp_commit();
        issueK(1, 1);
    }

    // per-lane ldmatrix address constants (identical math to R9)
    const int matA = lane >> 3;
    const int rA   = (lane & 7) + ((matA & 1) << 3);
    const int ckA  = matA >> 1;
    const uint32_t aRow = (uint32_t)(i0 + rA) * 128;
    const int swA = lane & 7;
    const int rB = lane & 7;
    const int matB = (lane >> 3) & 1;
    const uint32_t bRow = (uint32_t)(i0 + rB) * 128;

    float C[5][4];
#pragma unroll
    for (int t = 0; t < 5; ++t)
#pragma unroll
        for (int g = 0; g < 4; ++g) C[t][g] = 0.0f;

    const float scale = 1.0f / 256.0f;
    float* sd = reinterpret_cast<float*>(smA + SDOFF);
    const int r0l = lane >> 2, n0l = (lane & 3) * 2;

    for (int c = 0; c < NC; ++c) {
        if (c + 1 < NC) cp_wait1(); else cp_wait0();
        __syncthreads();                       // stage (c&1) visible CTA-wide

        // ---- compute chunk c (this warp: k-steps 2kh, 2kh+1; all 5 tiles) ----
        {
            const int kc = c & 3;
            const uint32_t qhi = smb + QOFF + (uint32_t)((p*2 + 0)*4 + kc) * 8192;
            const uint32_t qlo = smb + QOFF + (uint32_t)((p*2 + 1)*4 + kc) * 8192;
            const uint32_t khi = smb + KOFF + (uint32_t)(c & 1) * KCHUNK
                               + (uint32_t)(p * 2) * KTILE;
            const uint32_t klo = khi + KTILE;
#pragma unroll
            for (int kk = 0; kk < 2; ++kk) {
                const int k = 2 * kh + kk;
                uint32_t aH[4], aL[4], bH[2], bL[2];
                const uint32_t ao = aRow + ((uint32_t)((2*k + ckA) ^ swA) << 4);
                ldmA(aH, qhi + ao);
                ldmA(aL, qlo + ao);
                const uint32_t bo = bRow + ((uint32_t)((2*k + matB) ^ rB) << 4);
#pragma unroll
                for (int t = 0; t < 5; ++t) {
                    const uint32_t toff = (uint32_t)t * 1024;
                    ldmB(bH, khi + bo + toff);
                    mma16816(C[t], aH, bH);
                    mma16816(C[t], aL, bH);
                    ldmB(bL, klo + bo + toff);
                    mma16816(C[t], aH, bL);
                }
            }
        }

        // ---- epilogue after last kc of a dy: combine k-halves through sd ----
        if ((c & 3) == 3) {
            const int dyi = dyimin + (c >> 2);
            if (kh == 0) {
#pragma unroll
                for (int t = 0; t < 5; ++t)
#pragma unroll
                    for (int g = 0; g < 4; ++g) {
                        const int row = r0l + ((g & 2) ? 8 : 0);
                        const int col = n0l + (g & 1);
                        const int dxi = 8 * t + col - row;
                        if (dxi >= 0 && dxi < GG)
                            sd[dxi * WW + 2 * (i0 + row) + p] = C[t][g];
                        C[t][g] = 0.0f;
                    }
            }
            __syncthreads();                    // kh0 writes done
            if (kh == 1) {
#pragma unroll
                for (int t = 0; t < 5; ++t)
#pragma unroll
                    for (int g = 0; g < 4; ++g) {
                        const int row = r0l + ((g & 2) ? 8 : 0);
                        const int col = n0l + (g & 1);
                        const int dxi = 8 * t + col - row;
                        if (dxi >= 0 && dxi < GG)
                            sd[dxi * WW + 2 * (i0 + row) + p] += C[t][g];
                        C[t][g] = 0.0f;
                    }
            }
            __syncthreads();                    // sd complete
            const long pb = obase_bh + (long)(dyi * GG) * (HH * WW);
            for (int e = tid; e < GG * WW; e += NTHR) {
                out[pb + (long)(e >> 7) * (HH * WW) + (e & 127)] = sd[e] * scale;
            }
        }

        __syncthreads();                        // stage (c&1) drained; sd read
        if (c + 2 < NC) issueK(c + 2, c & 1);
    }
}

extern "C" void kernel_launch(void* const* d_in, const int* in_sizes, int n_in,
                              void* d_out, int out_size)
{
    const float* in1 = (const float*)d_in[0];
    const float* in2 = (const float*)d_in[1];
    float* out = (float*)d_out;
    (void)in_sizes; (void)n_in; (void)out_size;

    cudaFuncSetAttribute(corr_mma_kernel,
                         cudaFuncAttributeMaxDynamicSharedMemorySize, SMEM_REQ);

    dim3 pgrid(4, HH, CB * 2);
    prep_kernel<<<pgrid, 256>>>(in1, in2);

    dim3 grid(HH, CB);
    corr_mma_kernel<<<grid, NTHR, SMEM_REQ>>>(out);
}

// round 13
// speedup vs baseline: 1.2477x; 1.1476x over previous
#include <cuda_runtime.h>
#include <cuda_bf16.h>
#include <cstdint>

// FlowNet correlation — R12: R9 main kernel (256 thr, best measured) +
// persistent 148-CTA balanced task loop + R11's conflict-free prepass.
// out[b, dyi*21+dxi, h, w] = (1/256) * sum_c in1[b,c,h,w] * in2[b,c,h+dy,w+dx]
// Parity space: i = w>>1; band j - i = dxi-10 in [-10,10].
// Per (b,h,dy,par): 64x64x256 Gram restricted to 4 row-blocks x 5 col-tiles.
// Precision: bf16 hi/lo split, 3 MMA terms, fp32 accum.

#define CB   8
#define CC_  256
#define HH   96
#define WW   128
#define GG   21
#define DD   441
#define NTASK (HH * CB)     // 768
#define NCTA  148

#define QBLOB  131072L     // per (b,h):  [par][hl][kc][64 rows][128B]
#define KTILE  11264       // per (par,hl): 88 rows x 128B (halo rows zero)
#define KCHUNK 45056       // per kc: [par][hl] x KTILE
#define KBLOB  180224L     // per (b,r): 4 kc x KCHUNK

#define QOFF   0
#define KOFF   131072
#define SDOFF  221184                  // 21*128 f32 dump
#define SMEM_REQ 232064

__device__ __align__(128) char g1[(long)CB * HH * QBLOB];
__device__ __align__(128) char g2[(long)CB * HH * KBLOB];

// ---------------- helpers ----------------
__device__ __forceinline__ uint32_t smem_u32(const void* p) {
    uint32_t a;
    asm("{ .reg .u64 t; cvta.to.shared.u64 t, %1; cvt.u32.u64 %0, t; }"
        : "=r"(a) : "l"(p));
    return a;
}
__device__ __forceinline__ void cp16(uint32_t dst, const void* src) {
    asm volatile("cp.async.cg.shared.global [%0], [%1], 16;"
                 :: "r"(dst), "l"(src));
}
__device__ __forceinline__ void cp_commit() {
    asm volatile("cp.async.commit_group;" ::: "memory");
}
__device__ __forceinline__ void cp_wait1() {
    asm volatile("cp.async.wait_group 1;" ::: "memory");
}
__device__ __forceinline__ void cp_wait0() {
    asm volatile("cp.async.wait_group 0;" ::: "memory");
}
__device__ __forceinline__ void ldmA(uint32_t a[4], uint32_t addr) {
    asm volatile("ldmatrix.sync.aligned.m8n8.x4.shared.b16 {%0,%1,%2,%3}, [%4];"
        : "=r"(a[0]), "=r"(a[1]), "=r"(a[2]), "=r"(a[3]) : "r"(addr));
}
__device__ __forceinline__ void ldmB(uint32_t bq[2], uint32_t addr) {
    asm volatile("ldmatrix.sync.aligned.m8n8.x2.shared.b16 {%0,%1}, [%2];"
        : "=r"(bq[0]), "=r"(bq[1]) : "r"(addr));
}
__device__ __forceinline__ void mma16816(float c[4], const uint32_t a[4],
                                         const uint32_t bq[2]) {
    asm volatile("mma.sync.aligned.m16n8k16.row.col.f32.bf16.bf16.f32 "
        "{%0,%1,%2,%3}, {%4,%5,%6,%7}, {%8,%9}, {%0,%1,%2,%3};"
        : "+f"(c[0]), "+f"(c[1]), "+f"(c[2]), "+f"(c[3])
        : "r"(a[0]), "r"(a[1]), "r"(a[2]), "r"(a[3]), "r"(bq[0]), "r"(bq[1]));
}
__device__ __forceinline__ unsigned short cvt_hl(float v, int hl) {
    const __nv_bfloat16 h = __float2bfloat16(v);
    if (!hl) return __bfloat16_as_ushort(h);
    return __bfloat16_as_ushort(__float2bfloat16(v - __bfloat162float(h)));
}

// ---------------- prepass: fp32 -> swizzled bf16 hi/lo parity tiles ----------
__global__ __launch_bounds__(256)
void prep_kernel(const float* __restrict__ in1,
                 const float* __restrict__ in2)
{
    __shared__ float st[64][133];          // 133 pad: 2-way read conflicts
    const int kc = blockIdx.x, hh = blockIdx.y;
    const int b = blockIdx.z >> 1, inp = blockIdx.z & 1;
    const float* src = inp ? in2 : in1;

    for (int i = threadIdx.x; i < 64 * 32; i += 256) {
        const int c = i >> 5, q = i & 31;
        const float4 v = *reinterpret_cast<const float4*>(
            src + (((long)(b * CC_ + kc * 64 + c)) * HH + hh) * WW + 4 * q);
        st[c][4*q+0] = v.x; st[c][4*q+1] = v.y;
        st[c][4*q+2] = v.z; st[c][4*q+3] = v.w;
    }
    __syncthreads();

    if (!inp) {
        char* base = g1 + (long)(b * HH + hh) * QBLOB;
        for (int e = threadIdx.x; e < 2048; e += 256) {
            const int c8 = e & 7, s = (e >> 3) & 63;
            const int hl = (e >> 9) & 1, par = (e >> 10) & 1;
            const int w = 2 * s + par;
            uint32_t pk[4];
#pragma unroll
            for (int k = 0; k < 4; ++k) {
                const unsigned short u0 = cvt_hl(st[c8*8 + 2*k][w], hl);
                const unsigned short u1 = cvt_hl(st[c8*8 + 2*k + 1][w], hl);
                pk[k] = (uint32_t)u0 | ((uint32_t)u1 << 16);
            }
            char* tile = base + (long)(((par*2 + hl)*4 + kc)) * 8192;
            *reinterpret_cast<uint4*>(tile + s*128 + ((c8 ^ (s & 7)) << 4)) =
                make_uint4(pk[0], pk[1], pk[2], pk[3]);
        }
    } else {
        char* base = g2 + (long)(b * HH + hh) * KBLOB;
        for (int e = threadIdx.x; e < 2816; e += 256) {
            const int c8 = e & 7;
            const int jp = (e >> 3) % 88;
            const int hlp = e / (8 * 88);
            const int hl = hlp & 1, par = hlp >> 1;
            uint4 val = make_uint4(0u, 0u, 0u, 0u);
            if (jp >= 10 && jp < 74) {
                const int w = 2 * (jp - 10) + par;
                uint32_t pk[4];
#pragma unroll
                for (int k = 0; k < 4; ++k) {
                    const unsigned short u0 = cvt_hl(st[c8*8 + 2*k][w], hl);
                    const unsigned short u1 = cvt_hl(st[c8*8 + 2*k + 1][w], hl);
                    pk[k] = (uint32_t)u0 | ((uint32_t)u1 << 16);
                }
                val = make_uint4(pk[0], pk[1], pk[2], pk[3]);
            }
            char* tile = base + (long)(kc*4 + par*2 + hl) * KTILE;
            *reinterpret_cast<uint4*>(tile + jp*128 + ((c8 ^ (jp & 7)) << 4)) = val;
        }
    }
}

// ---------------- main kernel (persistent, 256 threads) ----------------
__global__ __launch_bounds__(256, 1)
void corr_mma_kernel(float* __restrict__ out)
{
    extern __shared__ char smraw[];
    const uint32_t rawS = smem_u32(smraw);
    const uint32_t smb = (rawS + 127) & ~127u;
    char* smA = smraw + (smb - rawS);

    const int tid = threadIdx.x, lane = tid & 31, wid = tid >> 5;
    const int p = wid & 1, i0 = (wid >> 1) * 16;

    // per-lane ldmatrix address constants (task-invariant)
    const int matA = lane >> 3;
    const int rA   = (lane & 7) + ((matA & 1) << 3);
    const int ckA  = matA >> 1;
    const uint32_t aRow = (uint32_t)(i0 + rA) * 128;
    const int swA = lane & 7;
    const int rB = lane & 7;
    const int matB = (lane >> 3) & 1;
    const uint32_t bRow = (uint32_t)(i0 + rB) * 128;

    const float scale = 1.0f / 256.0f;
    float* sd = reinterpret_cast<float*>(smA + SDOFF);
    const int r0l = lane >> 2, n0l = (lane & 3) * 2;

    float C[5][4];
#pragma unroll
    for (int t = 0; t < 5; ++t)
#pragma unroll
        for (int g = 0; g < 4; ++g) C[t][g] = 0.0f;

    // persistent task loop: stride-148 over g spreads h (task cost) evenly
    for (int g = blockIdx.x; g < NTASK; g += NCTA) {
        const int h = g >> 3;
        const int b = g & 7;

        const int dyimin = (h >= 20) ? 0 : ((21 - h) >> 1);
        const int dyimax = min(20, (115 - h) >> 1);
        const int nv = dyimax - dyimin + 1;
        const int NC = 4 * nv;

        const long obase_bh = (long)b * DD * HH * WW + (long)h * WW;

        // zero planes for invalid dy
        for (int dyi = 0; dyi < GG; ++dyi) {
            if (dyi >= dyimin && dyi <= dyimax) continue;
            const long pb = obase_bh + (long)(dyi * GG) * (HH * WW);
            for (int e = tid; e < GG * WW; e += 256) {
                out[pb + (long)(e >> 7) * (HH * WW) + (e & 127)] = 0.0f;
            }
        }

        // K chunk issue (one commit group per chunk)
        auto issueK = [&](int c, int stage) {
            const int vidx = c >> 2, kc = c & 3;
            const int r = h + 2 * (dyimin + vidx) - 20;
            const char* src = g2 + (long)(b * HH + r) * KBLOB + (long)kc * KCHUNK;
            const uint32_t dst = smb + KOFF + (uint32_t)stage * KCHUNK;
#pragma unroll
            for (int o = 0; o < 11; ++o) {
                const int t = tid + 256 * o;
                cp16(dst + (uint32_t)t * 16, src + (long)t * 16);
            }
            cp_commit();
        };

        // prologue: Q (+K0) as group 0, K1 as group 1
        {
            const char* qsrc = g1 + (long)(b * HH + h) * QBLOB;
#pragma unroll
            for (int o = 0; o < 32; ++o) {
                const int t = tid + 256 * o;
                cp16(smb + QOFF + (uint32_t)t * 16, qsrc + (long)t * 16);
            }
            const int r0v = h + 2 * dyimin - 20;
            const char* ks = g2 + (long)(b * HH + r0v) * KBLOB;
            const uint32_t dst = smb + KOFF;
#pragma unroll
            for (int o = 0; o < 11; ++o) {
                const int t = tid + 256 * o;
                cp16(dst + (uint32_t)t * 16, ks + (long)t * 16);
            }
            cp_commit();
            issueK(1, 1);
        }

        for (int c = 0; c < NC; ++c) {
            if (c + 1 < NC) cp_wait1(); else cp_wait0();
            __syncthreads();                   // stage (c&1) visible CTA-wide

            // ---- compute chunk c ----
            {
                const int kc = c & 3;
                const uint32_t qhi = smb + QOFF + (uint32_t)((p*2 + 0)*4 + kc) * 8192;
                const uint32_t qlo = smb + QOFF + (uint32_t)((p*2 + 1)*4 + kc) * 8192;
                const uint32_t khi = smb + KOFF + (uint32_t)(c & 1) * KCHUNK
                                   + (uint32_t)(p * 2) * KTILE;
                const uint32_t klo = khi + KTILE;
#pragma unroll
                for (int k = 0; k < 4; ++k) {
                    uint32_t aH[4], aL[4], bH[2], bL[2];
                    const uint32_t ao = aRow + ((uint32_t)((2*k + ckA) ^ swA) << 4);
                    ldmA(aH, qhi + ao);
                    ldmA(aL, qlo + ao);
                    const uint32_t bo = bRow + ((uint32_t)((2*k + matB) ^ rB) << 4);
#pragma unroll
                    for (int t = 0; t < 5; ++t) {
                        ldmB(bH, khi + bo + (uint32_t)t * 1024);
                        mma16816(C[t], aH, bH);
                        mma16816(C[t], aL, bH);
                        ldmB(bL, klo + bo + (uint32_t)t * 1024);
                        mma16816(C[t], aH, bL);
                    }
                }
            }

            // ---- epilogue after last kc of a dy ----
            if ((c & 3) == 3) {
                const int dyi = dyimin + (c >> 2);
#pragma unroll
                for (int t = 0; t < 5; ++t)
#pragma unroll
                    for (int g4 = 0; g4 < 4; ++g4) {
                        const int row = r0l + ((g4 & 2) ? 8 : 0);
                        const int col = n0l + (g4 & 1);
                        const int dxi = 8 * t + col - row;
                        if (dxi >= 0 && dxi < GG)
                            sd[dxi * WW + 2 * (i0 + row) + p] = C[t][g4] * scale;
                        C[t][g4] = 0.0f;
                    }
                __syncthreads();                // sd complete
                const long pb = obase_bh + (long)(dyi * GG) * (HH * WW);
                for (int e = tid; e < GG * WW; e += 256) {
                    out[pb + (long)(e >> 7) * (HH * WW) + (e & 127)] = sd[e];
                }
            }

            __syncthreads();                    // stage (c&1) drained; sd read
            if (c + 2 < NC) issueK(c + 2, c & 1);
        }
        // pipeline drained (wait0 at last chunk); barrier above makes
        // stage buffers safe for the next task's prologue.
    }
}

extern "C" void kernel_launch(void* const* d_in, const int* in_sizes, int n_in,
                              void* d_out, int out_size)
{
    const float* in1 = (const float*)d_in[0];
    const float* in2 = (const float*)d_in[1];
    float* out = (float*)d_out;
    (void)in_sizes; (void)n_in; (void)out_size;

    cudaFuncSetAttribute(corr_mma_kernel,
                         cudaFuncAttributeMaxDynamicSharedMemorySize, SMEM_REQ);

    dim3 pgrid(4, HH, CB * 2);
    prep_kernel<<<pgrid, 256>>>(in1, in2);

    corr_mma_kernel<<<NCTA, 256, SMEM_REQ>>>(out);
}

// round 14
// speedup vs baseline: 1.4101x; 1.1301x over previous
#include <cuda_runtime.h>
#include <cuda_bf16.h>
#include <cstdint>

// FlowNet correlation — R13: tf32 single-pass banded parity-space Gram.
// out[b, dyi*21+dxi, h, w] = (1/256) * sum_c in1[b,c,h,w] * in2[b,c,h+dy,w+dx]
// Parity space: i = w>>1; band j - i = dxi-10 in [-10,10].
// mma.sync.m16n8k8.tf32 (sm_80 baseline PTX): 1.5x fewer tensor instructions
// than bf16 3-term at identical operand bytes. Operands stored FRAGMENT-PACKED
// by the prepass: A frag = per-lane 16B (ld.shared.v4), B frag = per-lane 8B
// (ld.shared.v2); 11 disjoint 8-col B windows tile the 88-col band exactly.

#define CB   8
#define CC_  256
#define HH   96
#define WW   128
#define GG   21
#define DD   441
#define NTASK (HH * CB)
#define NCTA  148

#define QBLOB  131072L     // per (b,h): [par][kc][rb][ks] x 512B fragments
#define KCHUNK 45056       // per kc:    [par][u][ks] x 256B fragments
#define KBLOB  180224L     // per (b,r): 4 kc x KCHUNK

#define QOFF   0
#define KOFF   131072
#define SDOFF  221184                  // 21*128 f32 dump
#define SMEM_REQ 232064

__device__ __align__(128) char g1[(long)CB * HH * QBLOB];
__device__ __align__(128) char g2[(long)CB * HH * KBLOB];

// ---------------- helpers ----------------
__device__ __forceinline__ uint32_t smem_u32(const void* p) {
    uint32_t a;
    asm("{ .reg .u64 t; cvta.to.shared.u64 t, %1; cvt.u32.u64 %0, t; }"
        : "=r"(a) : "l"(p));
    return a;
}
__device__ __forceinline__ void cp16(uint32_t dst, const void* src) {
    asm volatile("cp.async.cg.shared.global [%0], [%1], 16;"
                 :: "r"(dst), "l"(src));
}
__device__ __forceinline__ void cp_commit() {
    asm volatile("cp.async.commit_group;" ::: "memory");
}
__device__ __forceinline__ void cp_wait1() {
    asm volatile("cp.async.wait_group 1;" ::: "memory");
}
__device__ __forceinline__ void cp_wait0() {
    asm volatile("cp.async.wait_group 0;" ::: "memory");
}
__device__ __forceinline__ void ldsV4(uint32_t r[4], uint32_t addr) {
    asm volatile("ld.shared.v4.u32 {%0,%1,%2,%3}, [%4];"
        : "=r"(r[0]), "=r"(r[1]), "=r"(r[2]), "=r"(r[3]) : "r"(addr));
}
__device__ __forceinline__ void ldsV2(uint32_t r[2], uint32_t addr) {
    asm volatile("ld.shared.v2.u32 {%0,%1}, [%2];"
        : "=r"(r[0]), "=r"(r[1]) : "r"(addr));
}
__device__ __forceinline__ void mma_tf32(float c[4], const uint32_t a[4],
                                         const uint32_t b[2]) {
    asm volatile("mma.sync.aligned.m16n8k8.row.col.f32.tf32.tf32.f32 "
        "{%0,%1,%2,%3}, {%4,%5,%6,%7}, {%8,%9}, {%0,%1,%2,%3};"
        : "+f"(c[0]), "+f"(c[1]), "+f"(c[2]), "+f"(c[3])
        : "r"(a[0]), "r"(a[1]), "r"(a[2]), "r"(a[3]), "r"(b[0]), "r"(b[1]));
}
__device__ __forceinline__ uint32_t f2tf32(float v) {
    uint32_t r;
    asm("cvt.rna.tf32.f32 %0, %1;" : "=r"(r) : "f"(v));
    return r;
}

// ---------------- prepass: fp32 -> fragment-packed tf32 ----------------
__global__ __launch_bounds__(256)
void prep_kernel(const float* __restrict__ in1,
                 const float* __restrict__ in2)
{
    __shared__ float st[64][133];
    const int kc = blockIdx.x, hh = blockIdx.y;
    const int b = blockIdx.z >> 1, inp = blockIdx.z & 1;
    const float* src = inp ? in2 : in1;

    for (int i = threadIdx.x; i < 64 * 32; i += 256) {
        const int c = i >> 5, q = i & 31;
        const float4 v = *reinterpret_cast<const float4*>(
            src + (((long)(b * CC_ + kc * 64 + c)) * HH + hh) * WW + 4 * q);
        st[c][4*q+0] = v.x; st[c][4*q+1] = v.y;
        st[c][4*q+2] = v.z; st[c][4*q+3] = v.w;
    }
    __syncthreads();

    if (!inp) {
        // A fragments: m16k8, a0:(row,k) a1:(row+8,k) a2:(row,k+4) a3:(row+8,k+4)
        char* base = g1 + (long)(b * HH + hh) * QBLOB;
        for (int e = threadIdx.x; e < 2048; e += 256) {
            const int lane = e & 31;
            const int ks = (e >> 5) & 7;
            const int rb = (e >> 8) & 3;
            const int par = e >> 10;
            const int row = 16 * rb + (lane >> 2);
            const int cl = 8 * ks + (lane & 3);
            const int w0 = 2 * row + par;
            const int w1 = 2 * (row + 8) + par;
            uint4 v;
            v.x = f2tf32(st[cl][w0]);
            v.y = f2tf32(st[cl][w1]);
            v.z = f2tf32(st[cl + 4][w0]);
            v.w = f2tf32(st[cl + 4][w1]);
            *reinterpret_cast<uint4*>(
                base + (long)((((par*4 + kc)*4 + rb)*8 + ks) * 512 + lane * 16)) = v;
        }
    } else {
        // B fragments: k8n8 col-major, b0:(k=l&3, n=l>>2) b1:(k+4, n)
        char* base = g2 + (long)(b * HH + hh) * KBLOB + (long)kc * KCHUNK;
        for (int e = threadIdx.x; e < 5632; e += 256) {
            const int lane = e & 31;
            const int ks = (e >> 5) & 7;
            const int u = (e >> 8) % 11;
            const int par = e / 2816;
            const int j = 8 * u - 10 + (lane >> 2);
            const int cl = 8 * ks + (lane & 3);
            uint2 v = make_uint2(0u, 0u);
            if ((unsigned)j < 64u) {
                const int w = 2 * j + par;
                v.x = f2tf32(st[cl][w]);
                v.y = f2tf32(st[cl + 4][w]);
            }
            *reinterpret_cast<uint2*>(
                base + (long)(((par*11 + u)*8 + ks) * 256 + lane * 8)) = v;
        }
    }
}

// ---------------- main kernel (persistent, 256 threads) ----------------
__global__ __launch_bounds__(256, 1)
void corr_mma_kernel(float* __restrict__ out)
{
    extern __shared__ char smraw[];
    const uint32_t rawS = smem_u32(smraw);
    const uint32_t smb = (rawS + 127) & ~127u;
    char* smA = smraw + (smb - rawS);

    const int tid = threadIdx.x, lane = tid & 31, wid = tid >> 5;
    const int p = wid & 1, rb = wid >> 1;
    const int i0 = rb * 16;

    const float scale = 1.0f / 256.0f;
    float* sd = reinterpret_cast<float*>(smA + SDOFF);
    const int r0l = lane >> 2, n0l = (lane & 3) * 2;

    // task-invariant fragment address bases
    const uint32_t aLane = (uint32_t)lane * 16;
    const uint32_t bLane = (uint32_t)lane * 8;

    float C[5][4];
#pragma unroll
    for (int t = 0; t < 5; ++t)
#pragma unroll
        for (int g = 0; g < 4; ++g) C[t][g] = 0.0f;

    for (int g = blockIdx.x; g < NTASK; g += NCTA) {
        const int h = g >> 3;
        const int b = g & 7;

        const int dyimin = (h >= 20) ? 0 : ((21 - h) >> 1);
        const int dyimax = min(20, (115 - h) >> 1);
        const int nv = dyimax - dyimin + 1;
        const int NC = 4 * nv;

        const long obase_bh = (long)b * DD * HH * WW + (long)h * WW;

        // zero planes for invalid dy
        for (int dyi = 0; dyi < GG; ++dyi) {
            if (dyi >= dyimin && dyi <= dyimax) continue;
            const long pb = obase_bh + (long)(dyi * GG) * (HH * WW);
            for (int e = tid; e < GG * WW; e += 256) {
                out[pb + (long)(e >> 7) * (HH * WW) + (e & 127)] = 0.0f;
            }
        }

        auto issueK = [&](int c, int stage) {
            const int vidx = c >> 2, kc = c & 3;
            const int r = h + 2 * (dyimin + vidx) - 20;
            const char* src = g2 + (long)(b * HH + r) * KBLOB + (long)kc * KCHUNK;
            const uint32_t dst = smb + KOFF + (uint32_t)stage * KCHUNK;
#pragma unroll
            for (int o = 0; o < 11; ++o) {
                const int t = tid + 256 * o;
                cp16(dst + (uint32_t)t * 16, src + (long)t * 16);
            }
            cp_commit();
        };

        // prologue: Q (+K0) as group 0, K1 as group 1
        {
            const char* qsrc = g1 + (long)(b * HH + h) * QBLOB;
#pragma unroll
            for (int o = 0; o < 32; ++o) {
                const int t = tid + 256 * o;
                cp16(smb + QOFF + (uint32_t)t * 16, qsrc + (long)t * 16);
            }
            const int r0v = h + 2 * dyimin - 20;
            const char* ks = g2 + (long)(b * HH + r0v) * KBLOB;
            const uint32_t dst = smb + KOFF;
#pragma unroll
            for (int o = 0; o < 11; ++o) {
                const int t = tid + 256 * o;
                cp16(dst + (uint32_t)t * 16, ks + (long)t * 16);
            }
            cp_commit();
            issueK(1, 1);
        }

        for (int c = 0; c < NC; ++c) {
            if (c + 1 < NC) cp_wait1(); else cp_wait0();
            __syncthreads();                   // stage (c&1) visible CTA-wide

            // ---- compute chunk c: 8 ksteps x 5 tiles of m16n8k8 tf32 ----
            {
                const int kc = c & 3;
                const uint32_t aBase = smb + QOFF
                    + (uint32_t)(((p*4 + kc)*4 + rb)*8) * 512 + aLane;
                const uint32_t bBase = smb + KOFF + (uint32_t)(c & 1) * KCHUNK
                    + (uint32_t)((p*11 + 2*rb)*8) * 256 + bLane;
#pragma unroll
                for (int ks = 0; ks < 8; ++ks) {
                    uint32_t af[4];
                    ldsV4(af, aBase + (uint32_t)ks * 512);
#pragma unroll
                    for (int t = 0; t < 5; ++t) {
                        uint32_t bf[2];
                        ldsV2(bf, bBase + (uint32_t)t * 2048 + (uint32_t)ks * 256);
                        mma_tf32(C[t], af, bf);
                    }
                }
            }

            // ---- epilogue after last kc of a dy ----
            if ((c & 3) == 3) {
                const int dyi = dyimin + (c >> 2);
#pragma unroll
                for (int t = 0; t < 5; ++t)
#pragma unroll
                    for (int g4 = 0; g4 < 4; ++g4) {
                        const int row = r0l + ((g4 & 2) ? 8 : 0);
                        const int col = n0l + (g4 & 1);
                        const int dxi = 8 * t + col - row;
                        if (dxi >= 0 && dxi < GG)
                            sd[dxi * WW + 2 * (i0 + row) + p] = C[t][g4] * scale;
                        C[t][g4] = 0.0f;
                    }
                __syncthreads();                // sd complete
                const long pb = obase_bh + (long)(dyi * GG) * (HH * WW);
                for (int e = tid; e < GG * WW; e += 256) {
                    out[pb + (long)(e >> 7) * (HH * WW) + (e & 127)] = sd[e];
                }
            }

            __syncthreads();                    // stage (c&1) drained; sd read
            if (c + 2 < NC) issueK(c + 2, c & 1);
        }
    }
}

extern "C" void kernel_launch(void* const* d_in, const int* in_sizes, int n_in,
                              void* d_out, int out_size)
{
    const float* in1 = (const float*)d_in[0];
    const float* in2 = (const float*)d_in[1];
    float* out = (float*)d_out;
    (void)in_sizes; (void)n_in; (void)out_size;

    cudaFuncSetAttribute(corr_mma_kernel,
                         cudaFuncAttributeMaxDynamicSharedMemorySize, SMEM_REQ);

    dim3 pgrid(4, HH, CB * 2);
    prep_kernel<<<pgrid, 256>>>(in1, in2);

    corr_mma_kernel<<<NCTA, 256, SMEM_REQ>>>(out);
}

// round 15
// speedup vs baseline: 1.4975x; 1.0620x over previous
#include <cuda_runtime.h>
#include <cuda_bf16.h>
#include <cstdint>

// FlowNet correlation — R14: tf32 banded parity-space Gram, 2 CTAs/SM.
// out[b, dyi*21+dxi, h, w] = (1/256) * sum_c in1[b,c,h,w] * in2[b,c,h+dy,w+dx]
// CTA = (b, h, parity): 128 threads, 4 rb-warps, 110.7KB smem -> 2 CTAs
// co-resident per SM = two independent barrier domains feeding the tensor
// pipe (R10/R11 showed intra-CTA warp-adding fails; this decouples domains).
// Epilogue: direct predicated STG from C fragments (sd buffer + its 2
// barriers/dy removed). Prepass identical to R13 (fragment-packed tf32).

#define CB   8
#define CC_  256
#define HH   96
#define WW   128
#define GG   21
#define DD   441
#define NTASK (HH * CB * 2)   // 1536 (b,h,par)
#define NCTA  296

#define QBLOB  131072L     // per (b,h): [par][kc][rb][ks] x 512B A-fragments
#define KCHUNK 45056       // per (r,kc): [par][u][ks] x 256B B-fragments
#define KBLOB  180224L     // per (b,r): 4 kc x KCHUNK
#define KPART  22528       // per-parity half of a K chunk

#define QOFF   0
#define KOFF   65536       // per-parity Q = 64KB
#define SMEM_REQ 110720    // 65536 + 2*22528 + 128 slack

__device__ __align__(128) char g1[(long)CB * HH * QBLOB];
__device__ __align__(128) char g2[(long)CB * HH * KBLOB];

// ---------------- helpers ----------------
__device__ __forceinline__ uint32_t smem_u32(const void* p) {
    uint32_t a;
    asm("{ .reg .u64 t; cvta.to.shared.u64 t, %1; cvt.u32.u64 %0, t; }"
        : "=r"(a) : "l"(p));
    return a;
}
__device__ __forceinline__ void cp16(uint32_t dst, const void* src) {
    asm volatile("cp.async.cg.shared.global [%0], [%1], 16;"
                 :: "r"(dst), "l"(src));
}
__device__ __forceinline__ void cp_commit() {
    asm volatile("cp.async.commit_group;" ::: "memory");
}
__device__ __forceinline__ void cp_wait1() {
    asm volatile("cp.async.wait_group 1;" ::: "memory");
}
__device__ __forceinline__ void cp_wait0() {
    asm volatile("cp.async.wait_group 0;" ::: "memory");
}
__device__ __forceinline__ void ldsV4(uint32_t r[4], uint32_t addr) {
    asm volatile("ld.shared.v4.u32 {%0,%1,%2,%3}, [%4];"
        : "=r"(r[0]), "=r"(r[1]), "=r"(r[2]), "=r"(r[3]) : "r"(addr));
}
__device__ __forceinline__ void ldsV2(uint32_t r[2], uint32_t addr) {
    asm volatile("ld.shared.v2.u32 {%0,%1}, [%2];"
        : "=r"(r[0]), "=r"(r[1]) : "r"(addr));
}
__device__ __forceinline__ void mma_tf32(float c[4], const uint32_t a[4],
                                         const uint32_t b[2]) {
    asm volatile("mma.sync.aligned.m16n8k8.row.col.f32.tf32.tf32.f32 "
        "{%0,%1,%2,%3}, {%4,%5,%6,%7}, {%8,%9}, {%0,%1,%2,%3};"
        : "+f"(c[0]), "+f"(c[1]), "+f"(c[2]), "+f"(c[3])
        : "r"(a[0]), "r"(a[1]), "r"(a[2]), "r"(a[3]), "r"(b[0]), "r"(b[1]));
}
__device__ __forceinline__ uint32_t f2tf32(float v) {
    uint32_t r;
    asm("cvt.rna.tf32.f32 %0, %1;" : "=r"(r) : "f"(v));
    return r;
}

// ---------------- prepass: fp32 -> fragment-packed tf32 (unchanged R13) ----
__global__ __launch_bounds__(256)
void prep_kernel(const float* __restrict__ in1,
                 const float* __restrict__ in2)
{
    __shared__ float st[64][133];
    const int kc = blockIdx.x, hh = blockIdx.y;
    const int b = blockIdx.z >> 1, inp = blockIdx.z & 1;
    const float* src = inp ? in2 : in1;

    for (int i = threadIdx.x; i < 64 * 32; i += 256) {
        const int c = i >> 5, q = i & 31;
        const float4 v = *reinterpret_cast<const float4*>(
            src + (((long)(b * CC_ + kc * 64 + c)) * HH + hh) * WW + 4 * q);
        st[c][4*q+0] = v.x; st[c][4*q+1] = v.y;
        st[c][4*q+2] = v.z; st[c][4*q+3] = v.w;
    }
    __syncthreads();

    if (!inp) {
        char* base = g1 + (long)(b * HH + hh) * QBLOB;
        for (int e = threadIdx.x; e < 2048; e += 256) {
            const int lane = e & 31;
            const int ks = (e >> 5) & 7;
            const int rb = (e >> 8) & 3;
            const int par = e >> 10;
            const int row = 16 * rb + (lane >> 2);
            const int cl = 8 * ks + (lane & 3);
            const int w0 = 2 * row + par;
            const int w1 = 2 * (row + 8) + par;
            uint4 v;
            v.x = f2tf32(st[cl][w0]);
            v.y = f2tf32(st[cl][w1]);
            v.z = f2tf32(st[cl + 4][w0]);
            v.w = f2tf32(st[cl + 4][w1]);
            *reinterpret_cast<uint4*>(
                base + (long)((((par*4 + kc)*4 + rb)*8 + ks) * 512 + lane * 16)) = v;
        }
    } else {
        char* base = g2 + (long)(b * HH + hh) * KBLOB + (long)kc * KCHUNK;
        for (int e = threadIdx.x; e < 5632; e += 256) {
            const int lane = e & 31;
            const int ks = (e >> 5) & 7;
            const int u = (e >> 8) % 11;
            const int par = e / 2816;
            const int j = 8 * u - 10 + (lane >> 2);
            const int cl = 8 * ks + (lane & 3);
            uint2 v = make_uint2(0u, 0u);
            if ((unsigned)j < 64u) {
                const int w = 2 * j + par;
                v.x = f2tf32(st[cl][w]);
                v.y = f2tf32(st[cl + 4][w]);
            }
            *reinterpret_cast<uint2*>(
                base + (long)(((par*11 + u)*8 + ks) * 256 + lane * 8)) = v;
        }
    }
}

// ---------------- main kernel (persistent, 128 threads, 2 CTAs/SM) --------
__global__ __launch_bounds__(128, 2)
void corr_mma_kernel(float* __restrict__ out)
{
    extern __shared__ char smraw[];
    const uint32_t rawS = smem_u32(smraw);
    const uint32_t smb = (rawS + 127) & ~127u;

    const int tid = threadIdx.x, lane = tid & 31, rb = tid >> 5;
    const int i0 = rb * 16;

    const float scale = 1.0f / 256.0f;
    const int r0l = lane >> 2, n0l = (lane & 3) * 2;

    const uint32_t aLane = (uint32_t)lane * 16;
    const uint32_t bLane = (uint32_t)lane * 8;

    float C[5][4];
#pragma unroll
    for (int t = 0; t < 5; ++t)
#pragma unroll
        for (int g = 0; g < 4; ++g) C[t][g] = 0.0f;

    for (int g = blockIdx.x; g < NTASK; g += NCTA) {
        const int p = g & 1;
        const int b = (g >> 1) & 7;
        const int h = g >> 4;

        const int dyimin = (h >= 20) ? 0 : ((21 - h) >> 1);
        const int dyimax = min(20, (115 - h) >> 1);
        const int nv = dyimax - dyimin + 1;
        const int NC = 4 * nv;

        const long obase_bh = (long)b * DD * HH * WW + (long)h * WW;

        // zero this parity's elements of invalid-dy planes
        for (int dyi = 0; dyi < GG; ++dyi) {
            if (dyi >= dyimin && dyi <= dyimax) continue;
            const long pb = obase_bh + (long)(dyi * GG) * (HH * WW);
            for (int e = tid; e < GG * 64; e += 128) {
                out[pb + (long)(e >> 6) * (HH * WW) + 2 * (e & 63) + p] = 0.0f;
            }
        }

        auto issueK = [&](int c, int stage) {
            const int vidx = c >> 2, kc = c & 3;
            const int r = h + 2 * (dyimin + vidx) - 20;
            const char* src = g2 + (long)(b * HH + r) * KBLOB
                            + (long)kc * KCHUNK + (long)p * KPART;
            const uint32_t dst = smb + KOFF + (uint32_t)stage * KPART;
#pragma unroll
            for (int o = 0; o < 11; ++o) {
                const int t = tid + 128 * o;
                cp16(dst + (uint32_t)t * 16, src + (long)t * 16);
            }
            cp_commit();
        };

        // prologue: Q (+K0) as group 0, K1 as group 1
        {
            const char* qsrc = g1 + (long)(b * HH + h) * QBLOB + (long)p * 65536;
#pragma unroll
            for (int o = 0; o < 32; ++o) {
                const int t = tid + 128 * o;
                cp16(smb + QOFF + (uint32_t)t * 16, qsrc + (long)t * 16);
            }
            const int r0v = h + 2 * dyimin - 20;
            const char* ks = g2 + (long)(b * HH + r0v) * KBLOB + (long)p * KPART;
            const uint32_t dst = smb + KOFF;
#pragma unroll
            for (int o = 0; o < 11; ++o) {
                const int t = tid + 128 * o;
                cp16(dst + (uint32_t)t * 16, ks + (long)t * 16);
            }
            cp_commit();
            issueK(1, 1);
        }

        for (int c = 0; c < NC; ++c) {
            if (c + 1 < NC) cp_wait1(); else cp_wait0();
            __syncthreads();                   // stage (c&1) visible CTA-wide

            // ---- compute chunk c: 8 ksteps x 5 tiles of m16n8k8 tf32 ----
            {
                const int kc = c & 3;
                const uint32_t aBase = smb + QOFF
                    + (uint32_t)((kc*4 + rb)*8) * 512 + aLane;
                const uint32_t bBase = smb + KOFF + (uint32_t)(c & 1) * KPART
                    + (uint32_t)(2*rb*8) * 256 + bLane;
#pragma unroll
                for (int ks = 0; ks < 8; ++ks) {
                    uint32_t af[4];
                    ldsV4(af, aBase + (uint32_t)ks * 512);
#pragma unroll
                    for (int t = 0; t < 5; ++t) {
                        uint32_t bf[2];
                        ldsV2(bf, bBase + (uint32_t)t * 2048 + (uint32_t)ks * 256);
                        mma_tf32(C[t], af, bf);
                    }
                }
            }

            // ---- epilogue after last kc of a dy: direct predicated STG ----
            if ((c & 3) == 3) {
                const int dyi = dyimin + (c >> 2);
                const long pb = obase_bh + (long)(dyi * GG) * (HH * WW);
#pragma unroll
                for (int t = 0; t < 5; ++t)
#pragma unroll
                    for (int g4 = 0; g4 < 4; ++g4) {
                        const int row = r0l + ((g4 & 2) ? 8 : 0);
                        const int col = n0l + (g4 & 1);
                        const int dxi = 8 * t + col - row;
                        if (dxi >= 0 && dxi < GG)
                            out[pb + (long)dxi * (HH * WW) + 2 * (i0 + row) + p]
                                = C[t][g4] * scale;
                        C[t][g4] = 0.0f;
                    }
            }

            __syncthreads();                   // stage (c&1) drained
            if (c + 2 < NC) issueK(c + 2, c & 1);
        }
    }
}

extern "C" void kernel_launch(void* const* d_in, const int* in_sizes, int n_in,
                              void* d_out, int out_size)
{
    const float* in1 = (const float*)d_in[0];
    const float* in2 = (const float*)d_in[1];
    float* out = (float*)d_out;
    (void)in_sizes; (void)n_in; (void)out_size;

    cudaFuncSetAttribute(corr_mma_kernel,
                         cudaFuncAttributeMaxDynamicSharedMemorySize, SMEM_REQ);

    dim3 pgrid(4, HH, CB * 2);
    prep_kernel<<<pgrid, 256>>>(in1, in2);

    corr_mma_kernel<<<NCTA, 128, SMEM_REQ>>>(out);
}